// round 14
// baseline (speedup 1.0000x reference)
#include <cuda_runtime.h>
#include <cuda_fp16.h>
#include <math.h>
#include <stdint.h>

// ---------------------------------------------------------------------------
// ReDrafterHead: 2-layer GRU draft head + big vocab projection.
// B=64, HIDDEN=4096, DH=512, VOCAB=50257, NUM_DRAFT=4.
//
// Round 14:
//  - gru: 64 CTAs, j-range 8 per CTA, gi+gh in one CTA (N=64: gi cols 0-31
//    via A1, gh cols 32-63 via A2; 24 real cols each). Combine fused in-CTA
//    (epi smem). 10 grid barriers with 64 arrivals (was 18 x 128).
//  - logits: unchanged single-fp16 HMMA (CTA 128x128, 2 CTAs/SM).
// ---------------------------------------------------------------------------

#define B_      64
#define HID     4096
#define DH      512
#define VOCAB   50257
#define NDRAFT  4
#define GRIDN   64
#define G3      1536

__device__ float  g_h0f[2][B_ * DH], g_h1f[2][B_ * DH];
__device__ __half g_h0h[2][B_ * DH], g_h0l[2][B_ * DH];
__device__ __half g_h1h[2][B_ * DH], g_h1l[2][B_ * DH];
__device__ __half g_xh[B_ * DH],  g_xl[B_ * DH];
__device__ float  g_part[8 * B_ * DH];      // ip split-K partials
__device__ __half g_Ah[B_ * NDRAFT * DH];   // logits A fp16, m = b*4+step
__device__ __half g_wih0h[G3 * DH], g_whh0h[G3 * DH];
__device__ __half g_wih1h[G3 * DH], g_whh1h[G3 * DH];
__device__ unsigned int g_bcount;           // monotonic barrier counter

__device__ __forceinline__ float sigmoidf_(float v) { return 1.0f / (1.0f + __expf(-v)); }

__device__ __forceinline__ uint32_t pack_f16x2(__half lo, __half hi) {
    return ((uint32_t)__half_as_ushort(hi) << 16) | (uint32_t)__half_as_ushort(lo);
}
__device__ __forceinline__ uint32_t smem_to_u32(const void* p) {
    uint32_t a;
    asm("{ .reg .u64 t; cvta.to.shared.u64 t, %1; cvt.u32.u64 %0, t; }" : "=r"(a) : "l"(p));
    return a;
}
__device__ __forceinline__ void ldsm4(uint32_t* r, uint32_t addr) {
    asm volatile("ldmatrix.sync.aligned.m8n8.x4.shared.b16 {%0,%1,%2,%3}, [%4];"
        : "=r"(r[0]), "=r"(r[1]), "=r"(r[2]), "=r"(r[3]) : "r"(addr));
}
__device__ __forceinline__ void mma16816h(float* d, const uint32_t* a, const uint32_t* b) {
    asm volatile("mma.sync.aligned.m16n8k16.row.col.f32.f16.f16.f32 "
        "{%0,%1,%2,%3}, {%4,%5,%6,%7}, {%8,%9}, {%0,%1,%2,%3};"
        : "+f"(d[0]), "+f"(d[1]), "+f"(d[2]), "+f"(d[3])
        : "r"(a[0]), "r"(a[1]), "r"(a[2]), "r"(a[3]), "r"(b[0]), "r"(b[1]));
}

// Grid-wide barrier: monotonic counter (graph-replay safe; GRIDN co-resident).
__device__ __forceinline__ void grid_barrier(int tid) {
    __syncthreads();
    if (tid == 0) {
        __threadfence();
        unsigned int old = atomicAdd(&g_bcount, 1u);
        unsigned int target = (old / GRIDN + 1u) * GRIDN;
        unsigned int v;
        do {
            asm volatile("ld.acquire.gpu.global.u32 %0, [%1];" : "=r"(v) : "l"(&g_bcount));
        } while (v < target);
    }
    __syncthreads();
}

// ---------------------------------------------------------------------------
// Dynamic smem layout for gates (2-stage, 80B rows):
//   A1h: 0      + st*5120   A1l: 10240 + st*5120
//   A2h: 20480  + st*5120   A2l: 30720 + st*5120
//   W (64 rows: 0-31 WI incl pad, 32-63 WH incl pad): 40960 + st*5120
// total 51200. epi float[64][49] (12544 B) aliases offset 0 post-compute.
// ip phase uses [0, 16384).
#define GA_A(arr, st) ((arr) * 10240 + (st) * 5120)
#define GA_W(st)      (40960 + (st) * 5120)
#define GRU_SMEM      51200

// ---------------------------------------------------------------------------
// Fused gates+combine. CTA owns j-range [jb, jb+8).
// GEMM C[64 x 64]: cols 0-31 = gi via A1 (24 real), 32-63 = gh via A2.
// W rows r (region-local 0..31): gate = min(r,23)>>3, jj = min(r,23)&7.
// 8 warps: wm = w>>2 (m32), wn = w&3 (n16 tile); half = wn>>1 selects A1/A2.
// A fp16 hi+lo (2-term), W fp16 single.
// ---------------------------------------------------------------------------
__device__ __forceinline__ void gates_fused(
    char* smem, int tid, int jb,
    const __half* __restrict__ A1h, const __half* __restrict__ A1l,
    const __half* __restrict__ A2h, const __half* __restrict__ A2l,
    const __half* __restrict__ Wih, const __half* __restrict__ Whh,
    const float* __restrict__ bih, const float* __restrict__ bhh,
    const float* __restrict__ hOldf,
    float* __restrict__ hNewf, __half* __restrict__ hNewh, __half* __restrict__ hNewl,
    bool isL1, int step,
    const int* __restrict__ tids, const float* __restrict__ embed)
{
    const uint32_t sb = smem_to_u32(smem);
    const int lane = tid & 31;
    const int w    = tid >> 5;
    const int wm   = w >> 2;       // m32 half
    const int wn   = w & 3;        // n16 tile
    const int half = wn >> 1;      // 0 = gi (A1), 1 = gh (A2)
    const int gq   = lane >> 3;

    float d[2][2][4] = {};

    // loaders: A: i=0..3 -> A1h,A1l,A2h,A2l; row = tid>>2, ch = tid&3
    const int arow = tid >> 2;
    const int ach  = tid & 3;
    // W: r64 = tid>>2 (0-31 Wih, 32-63 Whh), rows >=24 in region clamped
    const int r64  = tid >> 2;
    const int rloc = r64 & 31;
    const int rclp = (rloc < 24) ? rloc : 23;
    const __half* wsrc = (r64 < 32) ? Wih : Whh;
    const long wgrow = (long)((rclp >> 3) * 512 + jb + (rclp & 7)) * DH;

    auto load_tile = [&](int t, int st) {
        const int k0 = t * 32;
        const __half* asrc[4] = { A1h, A1l, A2h, A2l };
        #pragma unroll
        for (int i = 0; i < 4; i++) {
            uint32_t dsta = sb + GA_A(i, st) + arow * 80 + ach * 16;
            asm volatile("cp.async.ca.shared.global [%0], [%1], 16;"
                         :: "r"(dsta), "l"(&asrc[i][arow * DH + k0 + ach * 8]));
        }
        uint32_t dstw = sb + GA_W(st) + r64 * 80 + ach * 16;
        asm volatile("cp.async.ca.shared.global [%0], [%1], 16;"
                     :: "r"(dstw), "l"(&wsrc[wgrow + k0 + ach * 8]));
        asm volatile("cp.async.commit_group;" ::: "memory");
    };

    auto compute = [&](int st) {
        const uint32_t aH = sb + GA_A(half * 2, st);
        const uint32_t aL = sb + GA_A(half * 2 + 1, st);
        const uint32_t wB = sb + GA_W(st) + half * (32 * 80);
        #pragma unroll
        for (int ks = 0; ks < 2; ks++) {
            uint32_t ahi[2][4], alo[2][4], bt[4];
            #pragma unroll
            for (int mi = 0; mi < 2; mi++) {
                int row = wm * 32 + mi * 16 + (lane & 15);
                int kc  = ks * 32 + (lane >> 4) * 16;
                ldsm4(ahi[mi], aH + row * 80 + kc);
                ldsm4(alo[mi], aL + row * 80 + kc);
            }
            {
                int rowB = (wn & 1) * 16 + (gq >> 1) * 8 + (lane & 7);
                int kcB  = ks * 32 + (gq & 1) * 16;
                ldsm4(bt, wB + rowB * 80 + kcB);
            }
            #pragma unroll
            for (int mi = 0; mi < 2; mi++)
                #pragma unroll
                for (int ni = 0; ni < 2; ni++) {
                    uint32_t bf[2] = { bt[2 * ni], bt[2 * ni + 1] };
                    mma16816h(d[mi][ni], ahi[mi], bf);
                    mma16816h(d[mi][ni], alo[mi], bf);
                }
        }
    };

    load_tile(0, 0);
    asm volatile("cp.async.wait_group 0;" ::: "memory");
    __syncthreads();

    #pragma unroll 1
    for (int t = 0; t < 16; t++) {
        const int st = t & 1;
        if (t + 1 < 16) load_tile(t + 1, 1 - st);
        compute(st);
        if (t + 1 < 16)
            asm volatile("cp.async.wait_group 0;" ::: "memory");
        __syncthreads();
    }

    // stage gates to epi (aliases stage buffers; compute fully done)
    float (*epi)[49] = reinterpret_cast<float(*)[49]>(smem);
    {
        #pragma unroll
        for (int mi = 0; mi < 2; mi++)
            #pragma unroll
            for (int ni = 0; ni < 2; ni++) {
                int r  = wm * 32 + mi * 16 + (lane >> 2);
                int cw = (wn & 1) * 16 + ni * 8 + (lane & 3) * 2;
                if (cw < 24) {
                    int col = half * 24 + cw;
                    epi[r][col]         = d[mi][ni][0];
                    epi[r][col + 1]     = d[mi][ni][1];
                    epi[r + 8][col]     = d[mi][ni][2];
                    epi[r + 8][col + 1] = d[mi][ni][3];
                }
            }
    }
    __syncthreads();

    // fused combine: 2 (m, j) pairs per thread (512 total)
    #pragma unroll
    for (int i = 0; i < 2; i++) {
        int idx = tid + i * 256;       // 0..511
        int m = idx >> 3, j = idx & 7, jj = jb + j;
        const float* E = epi[m];
        float r = sigmoidf_(E[j]      + bih[jj]        + E[24 + j] + bhh[jj]);
        float z = sigmoidf_(E[8 + j]  + bih[512 + jj]  + E[32 + j] + bhh[512 + jj]);
        float n = tanhf(E[16 + j] + bih[1024 + jj] + r * (E[40 + j] + bhh[1024 + jj]));
        float hn = (1.f - z) * n + z * hOldf[m * DH + jj];
        int o = m * DH + jj;
        hNewf[o] = hn;
        __half hi = __float2half(hn);
        hNewh[o] = hi;
        hNewl[o] = __float2half(hn - __half2float(hi));
        if (isL1) {
            g_Ah[(m * NDRAFT + step) * DH + jj] = hi;
            if (step < NDRAFT - 1) {
                float xv = embed[(long)tids[m * NDRAFT + step] * DH + jj];
                __half xh = __float2half(xv);
                g_xh[o] = xh;
                g_xl[o] = __float2half(xv - __half2float(xh));
            }
        }
    }
}

// ---------------------------------------------------------------------------
__global__ __launch_bounds__(256) void gru_fused(
    const float* __restrict__ hidden, const int* __restrict__ tids,
    const float* __restrict__ ip_w,  const float* __restrict__ ip_b,
    const float* __restrict__ w_ih0, const float* __restrict__ w_hh0,
    const float* __restrict__ b_ih0, const float* __restrict__ b_hh0,
    const float* __restrict__ w_ih1, const float* __restrict__ w_hh1,
    const float* __restrict__ b_ih1, const float* __restrict__ b_hh1,
    const float* __restrict__ embed)
{
    extern __shared__ char smem[];
    const int tid = threadIdx.x;
    const int c = blockIdx.x;

    // ---- phase -1: convert GRU weights to fp16 (once per call) ----
    for (int i = c * 256 + tid; i < G3 * DH; i += GRIDN * 256) {
        g_wih0h[i] = __float2half(w_ih0[i]);
        g_whh0h[i] = __float2half(w_hh0[i]);
        g_wih1h[i] = __float2half(w_ih1[i]);
        g_whh1h[i] = __float2half(w_hh1[i]);
    }

    // ---- phase 0: input projection partials (64x64 n-tile, 512-k slice) ----
    {
        float (*As)[64] = reinterpret_cast<float(*)[64]>(smem);
        float (*Ws)[64] = reinterpret_cast<float(*)[64]>(smem + 8192);
        const int n0 = (c & 7) * 64;
        const int kbase = (c >> 3) * 512;
        const int ty = tid >> 4, tx = tid & 15;
        float acc[4][4] = {};
        for (int kt = 0; kt < 512; kt += 32) {
            #pragma unroll
            for (int i = 0; i < 2; i++) {
                int f = tid + i * 256;
                int m = f >> 3;
                int kq = (f & 7) << 2;
                float4 va = *reinterpret_cast<const float4*>(&hidden[m * HID + kbase + kt + kq]);
                As[kq + 0][m] = va.x; As[kq + 1][m] = va.y;
                As[kq + 2][m] = va.z; As[kq + 3][m] = va.w;
                float4 vw = *reinterpret_cast<const float4*>(&ip_w[(n0 + m) * HID + kbase + kt + kq]);
                Ws[kq + 0][m] = vw.x; Ws[kq + 1][m] = vw.y;
                Ws[kq + 2][m] = vw.z; Ws[kq + 3][m] = vw.w;
            }
            __syncthreads();
            #pragma unroll
            for (int kk = 0; kk < 32; kk++) {
                float a[4], b[4];
                #pragma unroll
                for (int i = 0; i < 4; i++) { a[i] = As[kk][ty * 4 + i]; b[i] = Ws[kk][tx * 4 + i]; }
                #pragma unroll
                for (int i = 0; i < 4; i++)
                    #pragma unroll
                    for (int j = 0; j < 4; j++) acc[i][j] += a[i] * b[j];
            }
            __syncthreads();
        }
        float* part = g_part + (c >> 3) * (B_ * DH);
        #pragma unroll
        for (int i = 0; i < 4; i++)
            #pragma unroll
            for (int j = 0; j < 4; j++)
                part[(ty * 4 + i) * DH + n0 + tx * 4 + j] = acc[i][j];
    }
    grid_barrier(tid);

    // ---- phase 1: reduce 8 partials + bias; init slot 0 + x = 0 ----
    #pragma unroll
    for (int i = 0; i < 2; i++) {
        int idx = c * 512 + tid + i * 256;
        float s = 0.f;
        #pragma unroll
        for (int p = 0; p < 8; p++) s += g_part[p * (B_ * DH) + idx];
        s += ip_b[idx & (DH - 1)];
        g_h0f[0][idx] = s;
        g_h1f[0][idx] = s;
        __half hi = __float2half(s);
        __half lo = __float2half(s - __half2float(hi));
        g_h0h[0][idx] = hi; g_h0l[0][idx] = lo;
        g_h1h[0][idx] = hi; g_h1l[0][idx] = lo;
        g_xh[idx] = __float2half(0.f);
        g_xl[idx] = __float2half(0.f);
    }
    grid_barrier(tid);

    // ---- 4 draft steps x 2 GRU layers, combine fused, 1 barrier/layer ----
    const int jb = c * 8;
    for (int step = 0; step < NDRAFT; step++) {
        const int p = step & 1;
        // layer 0: gi = x @ Wih0^T, gh = h0[p] @ Whh0^T -> h0[1-p]
        gates_fused(smem, tid, jb,
                    g_xh, g_xl, g_h0h[p], g_h0l[p],
                    g_wih0h, g_whh0h, b_ih0, b_hh0,
                    g_h0f[p], g_h0f[1 - p], g_h0h[1 - p], g_h0l[1 - p],
                    false, step, tids, embed);
        grid_barrier(tid);
        // layer 1: gi = h0[1-p] @ Wih1^T, gh = h1[p] @ Whh1^T -> h1[1-p]
        gates_fused(smem, tid, jb,
                    g_h0h[1 - p], g_h0l[1 - p], g_h1h[p], g_h1l[p],
                    g_wih1h, g_whh1h, b_ih1, b_hh1,
                    g_h1f[p], g_h1f[1 - p], g_h1h[1 - p], g_h1l[1 - p],
                    true, step, tids, embed);
        grid_barrier(tid);
    }
}

// ---------------------------------------------------------------------------
// Logits GEMM via single fp16 mma.sync (fp32 accum) — round-10..12 proven.
// CTA tile 128(M) x 128(N) x 32(K); 8 warps (2 M x 4 N); warp tile 64x32.
// smem 40KB -> 2 CTAs/SM. grid (2, 393).
// ---------------------------------------------------------------------------
#define ROWB 80
#define AH_OFF(s) ((s) * 10240)
#define BH_OFF(s) (20480 + (s) * 10240)
#define LOGITS_SMEM 40960

__global__ __launch_bounds__(256, 2) void logits_mma(const float* __restrict__ W,
                                                     float* __restrict__ out)
{
    extern __shared__ char smem[];
    const uint32_t sbase = smem_to_u32(smem);
    const int tid  = threadIdx.x;
    const int lane = tid & 31;
    const int w    = tid >> 5;
    const int wm   = w >> 2;
    const int wn   = w & 3;
    const int m0   = blockIdx.x * 128;
    const int n0   = blockIdx.y * 128;

    float d[4][4][4];
    #pragma unroll
    for (int i = 0; i < 4; i++)
        #pragma unroll
        for (int j = 0; j < 4; j++)
            #pragma unroll
            for (int q = 0; q < 4; q++) d[i][j][q] = 0.f;

    float4 breg[4];

    auto cpasync_A = [&](int c, int s) {
        const int k0 = c * 32;
        #pragma unroll
        for (int i = 0; i < 2; i++) {
            int idx = tid + i * 256;
            int row = idx >> 2;
            int ch  = idx & 3;
            const __half* sh = &g_Ah[(m0 + row) * DH + k0 + ch * 8];
            uint32_t dh = sbase + AH_OFF(s) + row * ROWB + ch * 16;
            asm volatile("cp.async.ca.shared.global [%0], [%1], 16;" :: "r"(dh), "l"(sh));
        }
        asm volatile("cp.async.commit_group;" ::: "memory");
    };

    auto ldg_B = [&](int c) {
        const int k0 = c * 32;
        #pragma unroll
        for (int i = 0; i < 4; i++) {
            int idx = tid + i * 256;
            int row = idx >> 3;
            int col = (idx & 7) * 4;
            int vr = n0 + row;
            breg[i] = (vr < VOCAB)
                ? *reinterpret_cast<const float4*>(&W[(long)vr * DH + k0 + col])
                : make_float4(0.f, 0.f, 0.f, 0.f);
        }
    };

    auto sts_B = [&](int s) {
        #pragma unroll
        for (int i = 0; i < 4; i++) {
            int idx = tid + i * 256;
            int row = idx >> 3;
            int col = (idx & 7) * 4;
            float4 v = breg[i];
            uint2 ph;
            ph.x = pack_f16x2(__float2half(v.x), __float2half(v.y));
            ph.y = pack_f16x2(__float2half(v.z), __float2half(v.w));
            *reinterpret_cast<uint2*>(smem + BH_OFF(s) + row * ROWB + col * 2) = ph;
        }
    };

    auto compute = [&](int s) {
        #pragma unroll
        for (int ks = 0; ks < 2; ks++) {
            uint32_t ah[4][4];
            #pragma unroll
            for (int mi = 0; mi < 4; mi++) {
                int row = wm * 64 + mi * 16 + (lane & 15);
                int kc  = ks * 32 + (lane >> 4) * 16;
                ldsm4(ah[mi], sbase + AH_OFF(s) + row * ROWB + kc);
            }
            uint32_t bh[4][2];
            #pragma unroll
            for (int nb = 0; nb < 2; nb++) {
                int gq  = lane >> 3;
                int row = wn * 32 + nb * 16 + (gq >> 1) * 8 + (lane & 7);
                int kc  = ks * 32 + (gq & 1) * 16;
                ldsm4(&bh[nb * 2][0], sbase + BH_OFF(s) + row * ROWB + kc);
            }
            #pragma unroll
            for (int mi = 0; mi < 4; mi++)
                #pragma unroll
                for (int ni = 0; ni < 4; ni++)
                    mma16816h(d[mi][ni], ah[mi], bh[ni]);
        }
    };

    cpasync_A(0, 0);
    ldg_B(0);
    sts_B(0);
    asm volatile("cp.async.wait_group 0;" ::: "memory");
    __syncthreads();

    #pragma unroll 1
    for (int c = 0; c < 16; c++) {
        int s = c & 1;
        if (c + 1 < 16) {
            cpasync_A(c + 1, 1 - s);
            ldg_B(c + 1);
        }
        compute(s);
        if (c + 1 < 16) {
            sts_B(1 - s);
            asm volatile("cp.async.wait_group 0;" ::: "memory");
        }
        __syncthreads();
    }

    const int g  = lane >> 2;
    const int i2 = (lane & 3) * 2;
    #pragma unroll
    for (int mi = 0; mi < 4; mi++) {
        int r0 = m0 + wm * 64 + mi * 16 + g;
        long rb0 = (long)r0 * VOCAB;
        long rb1 = (long)(r0 + 8) * VOCAB;
        #pragma unroll
        for (int ni = 0; ni < 4; ni++) {
            int col = n0 + wn * 32 + ni * 8 + i2;
            if (col < VOCAB) {
                out[rb0 + col] = d[mi][ni][0];
                out[rb1 + col] = d[mi][ni][2];
                if (col + 1 < VOCAB) {
                    out[rb0 + col + 1] = d[mi][ni][1];
                    out[rb1 + col + 1] = d[mi][ni][3];
                }
            }
        }
    }
}

// ---------------------------------------------------------------------------
extern "C" void kernel_launch(void* const* d_in, const int* in_sizes, int n_in,
                              void* d_out, int out_size)
{
    const float* hidden = (const float*)d_in[0];
    const int*   tids   = (const int*)  d_in[1];
    const float* ip_w   = (const float*)d_in[2];
    const float* ip_b   = (const float*)d_in[3];
    const float* w_ih0  = (const float*)d_in[4];
    const float* w_hh0  = (const float*)d_in[5];
    const float* b_ih0  = (const float*)d_in[6];
    const float* b_hh0  = (const float*)d_in[7];
    const float* w_ih1  = (const float*)d_in[8];
    const float* w_hh1  = (const float*)d_in[9];
    const float* b_ih1  = (const float*)d_in[10];
    const float* b_hh1  = (const float*)d_in[11];
    const float* embed  = (const float*)d_in[12];
    const float* out_w  = (const float*)d_in[13];
    float* out = (float*)d_out;

    cudaFuncSetAttribute(gru_fused, cudaFuncAttributeMaxDynamicSharedMemorySize, GRU_SMEM);
    cudaFuncSetAttribute(logits_mma, cudaFuncAttributeMaxDynamicSharedMemorySize, LOGITS_SMEM);

    gru_fused<<<GRIDN, 256, GRU_SMEM>>>(hidden, tids, ip_w, ip_b,
                                        w_ih0, w_hh0, b_ih0, b_hh0,
                                        w_ih1, w_hh1, b_ih1, b_hh1, embed);

    logits_mma<<<dim3(2, (VOCAB + 127) / 128), 256, LOGITS_SMEM>>>(out_w, out);
}

// round 15
// speedup vs baseline: 1.1356x; 1.1356x over previous
#include <cuda_runtime.h>
#include <cuda_fp16.h>
#include <math.h>
#include <stdint.h>

// ---------------------------------------------------------------------------
// ReDrafterHead: 2-layer GRU draft head + big vocab projection.
// B=64, HIDDEN=4096, DH=512, VOCAB=50257, NUM_DRAFT=4.
//
// Round 15 (= round 12 + barrier surgery):
//  - gemm/combine dependency is pairwise (gi CTA c <-> gh CTA c+64):
//    pair barrier (2 arrivals) + combine by gi-CTA only. Global barriers
//    18 -> 10. gi gates stay in SMEM (only gh half via global).
//  - h states double-buffered (needed since combine is no longer globally
//    ordered). GEMM bodies and logits_mma identical to round 12 (best).
// ---------------------------------------------------------------------------

#define B_      64
#define HID     4096
#define DH      512
#define VOCAB   50257
#define NDRAFT  4
#define GRIDN   128
#define G3      1536

__device__ float  g_h0f[2][B_ * DH], g_h1f[2][B_ * DH];
__device__ __half g_h0h[2][B_ * DH], g_h0l[2][B_ * DH];
__device__ __half g_h1h[2][B_ * DH], g_h1l[2][B_ * DH];
__device__ __half g_xh[B_ * DH],  g_xl[B_ * DH];
__device__ float  g_gates[B_ * 3072];       // only gh half (cols 1536+) used
__device__ float  g_part[16 * B_ * DH];     // ip split-K partials
__device__ __half g_Ah[B_ * NDRAFT * DH];   // logits A fp16, m = b*4+step
__device__ __half g_wih0h[G3 * DH], g_whh0h[G3 * DH];
__device__ __half g_wih1h[G3 * DH], g_whh1h[G3 * DH];
__device__ unsigned int g_bcount;           // global barrier counter
__device__ unsigned int g_pair[64];         // per-pair barrier counters

__device__ __forceinline__ float sigmoidf_(float v) { return 1.0f / (1.0f + __expf(-v)); }

__device__ __forceinline__ uint32_t pack_f16x2(__half lo, __half hi) {
    return ((uint32_t)__half_as_ushort(hi) << 16) | (uint32_t)__half_as_ushort(lo);
}
__device__ __forceinline__ uint32_t smem_to_u32(const void* p) {
    uint32_t a;
    asm("{ .reg .u64 t; cvta.to.shared.u64 t, %1; cvt.u32.u64 %0, t; }" : "=r"(a) : "l"(p));
    return a;
}
__device__ __forceinline__ void ldsm4(uint32_t* r, uint32_t addr) {
    asm volatile("ldmatrix.sync.aligned.m8n8.x4.shared.b16 {%0,%1,%2,%3}, [%4];"
        : "=r"(r[0]), "=r"(r[1]), "=r"(r[2]), "=r"(r[3]) : "r"(addr));
}
__device__ __forceinline__ void mma16816h(float* d, const uint32_t* a, const uint32_t* b) {
    asm volatile("mma.sync.aligned.m16n8k16.row.col.f32.f16.f16.f32 "
        "{%0,%1,%2,%3}, {%4,%5,%6,%7}, {%8,%9}, {%0,%1,%2,%3};"
        : "+f"(d[0]), "+f"(d[1]), "+f"(d[2]), "+f"(d[3])
        : "r"(a[0]), "r"(a[1]), "r"(a[2]), "r"(a[3]), "r"(b[0]), "r"(b[1]));
}

// Global grid barrier (monotonic, graph-replay safe; GRIDN co-resident).
__device__ __forceinline__ void grid_barrier(int tid) {
    __syncthreads();
    if (tid == 0) {
        __threadfence();
        unsigned int old = atomicAdd(&g_bcount, 1u);
        unsigned int target = (old / GRIDN + 1u) * GRIDN;
        unsigned int v;
        do {
            asm volatile("ld.acquire.gpu.global.u32 %0, [%1];" : "=r"(v) : "l"(&g_bcount));
        } while (v < target);
    }
    __syncthreads();
}

// Pair barrier: 2 arrivals (gi CTA c and gh CTA c+64), monotonic counter.
__device__ __forceinline__ void pair_barrier(int pidx, int tid) {
    __syncthreads();
    if (tid == 0) {
        __threadfence();
        unsigned int old = atomicAdd(&g_pair[pidx], 1u);
        unsigned int target = (old / 2u + 1u) * 2u;
        unsigned int v;
        do {
            asm volatile("ld.acquire.gpu.global.u32 %0, [%1];" : "=r"(v) : "l"(&g_pair[pidx]));
        } while (v < target);
    }
    __syncthreads();
}

// ---------------------------------------------------------------------------
struct SmemIP { float As[32][64]; float Ws[32][64]; };
// Gates HMMA stage buffers (round 12): 80B rows, conflict-free ldsm.
struct SmemGa { __half Ahi[2][64][40]; __half Alo[2][64][40]; __half W[2][32][40]; };
#define GA_AHI(st) ((st) * 5120)
#define GA_ALO(st) (10240 + (st) * 5120)
#define GA_W(st)   (20480 + (st) * 2560)

// ---------------------------------------------------------------------------
// Gates GEMM via HMMA (round-12 body): C[64 x 24(pad 32)] = A * Wg^T.
// A = (Ahi + Alo) fp16 2-term; W fp16. jr = j-range base (8 wide).
// If epi != nullptr (gi CTA): stage results to SMEM epi[64][25].
// Else (gh CTA): store to g_gates at col 1536 + gate*512 + jr + j.
// ---------------------------------------------------------------------------
__device__ __forceinline__ void gates_mma(
    SmemGa& s, int tid, int jr,
    const __half* __restrict__ Ahi, const __half* __restrict__ Alo,
    const __half* __restrict__ Wg, float (*epi)[25])
{
    const uint32_t sb = smem_to_u32(&s);
    const int lane = tid & 31;
    const int w  = tid >> 5;
    const int wm = w >> 2;     // 0..1
    const int wn = w & 3;      // 0..3
    const int ng = wn >> 1;    // n16 group
    const int p  = wn & 1;     // n8 within group
    const int gq = lane >> 3;

    float d[2][4] = {};

    const int arow = tid >> 2;             // 0..63
    const int ach  = tid & 3;              // 16B chunk
    int gidx = 0;
    if (tid < 128) {
        int r = tid >> 2;                  // 0..31
        int gate = (r < 24) ? (r >> 3) : 0;
        int jj   = (r < 24) ? (r & 7) : (r - 24);
        gidx = gate * 512 + jr + jj;
    }

    auto load_tile = [&](int t, int st) {
        const int k0 = t * 32;
        uint32_t da = sb + GA_AHI(st) + arow * 80 + ach * 16;
        asm volatile("cp.async.ca.shared.global [%0], [%1], 16;"
                     :: "r"(da), "l"(&Ahi[arow * DH + k0 + ach * 8]));
        uint32_t dl = sb + GA_ALO(st) + arow * 80 + ach * 16;
        asm volatile("cp.async.ca.shared.global [%0], [%1], 16;"
                     :: "r"(dl), "l"(&Alo[arow * DH + k0 + ach * 8]));
        if (tid < 128) {
            uint32_t dw = sb + GA_W(st) + (tid >> 2) * 80 + (tid & 3) * 16;
            asm volatile("cp.async.ca.shared.global [%0], [%1], 16;"
                         :: "r"(dw), "l"(&Wg[(long)gidx * DH + k0 + (tid & 3) * 8]));
        }
        asm volatile("cp.async.commit_group;" ::: "memory");
    };

    auto compute = [&](int st) {
        #pragma unroll
        for (int ks = 0; ks < 2; ks++) {
            uint32_t ahi2[2][4], alo2[2][4], bt[4];
            #pragma unroll
            for (int mi = 0; mi < 2; mi++) {
                int row = wm * 32 + mi * 16 + (lane & 15);
                int kc  = ks * 32 + (lane >> 4) * 16;
                ldsm4(ahi2[mi], sb + GA_AHI(st) + row * 80 + kc);
                ldsm4(alo2[mi], sb + GA_ALO(st) + row * 80 + kc);
            }
            {
                int rowB = ng * 16 + (gq >> 1) * 8 + (lane & 7);
                int kcB  = ks * 32 + (gq & 1) * 16;
                ldsm4(bt, sb + GA_W(st) + rowB * 80 + kcB);
            }
            uint32_t bf[2] = { bt[2 * p], bt[2 * p + 1] };
            #pragma unroll
            for (int mi = 0; mi < 2; mi++) {
                mma16816h(d[mi], ahi2[mi], bf);
                mma16816h(d[mi], alo2[mi], bf);
            }
        }
    };

    load_tile(0, 0);
    asm volatile("cp.async.wait_group 0;" ::: "memory");
    __syncthreads();

    #pragma unroll 1
    for (int t = 0; t < 16; t++) {
        const int st = t & 1;
        if (t + 1 < 16) load_tile(t + 1, 1 - st);
        compute(st);
        if (t + 1 < 16)
            asm volatile("cp.async.wait_group 0;" ::: "memory");
        __syncthreads();
    }

    // epilogue (skip wn==3 padding)
    if (wn < 3) {
        if (epi) {
            // gi: stage to SMEM (aliases stage buffers; compute done)
            const int cb = wn * 8 + (lane & 3) * 2;
            #pragma unroll
            for (int mi = 0; mi < 2; mi++) {
                int r = wm * 32 + mi * 16 + (lane >> 2);
                epi[r][cb]         = d[mi][0];
                epi[r][cb + 1]     = d[mi][1];
                epi[r + 8][cb]     = d[mi][2];
                epi[r + 8][cb + 1] = d[mi][3];
            }
        } else {
            // gh: store to global gate buffer
            const int colb = 1536 + wn * 512 + jr + (lane & 3) * 2;
            #pragma unroll
            for (int mi = 0; mi < 2; mi++) {
                int r = wm * 32 + mi * 16 + (lane >> 2);
                float* gr = g_gates + r * 3072;
                gr[colb]     = d[mi][0];
                gr[colb + 1] = d[mi][1];
                gr += 8 * 3072;
                gr[colb]     = d[mi][2];
                gr[colb + 1] = d[mi][3];
            }
        }
    }
    __syncthreads();
}

// ---------------------------------------------------------------------------
// Combine (gi CTA only): j-range [jb, jb+8), all 64 m; 2 elems/thread.
// gi gates from SMEM epi; gh gates from g_gates (cols 1536+).
// ---------------------------------------------------------------------------
__device__ __forceinline__ void combine_gi(
    float (*epi)[25], int tid, int jb,
    const float* __restrict__ bih, const float* __restrict__ bhh,
    const float* __restrict__ hOldf,
    float* __restrict__ hNewf, __half* __restrict__ hNewh, __half* __restrict__ hNewl,
    bool isL1, int step,
    const int* __restrict__ tids, const float* __restrict__ embed)
{
    #pragma unroll
    for (int i = 0; i < 2; i++) {
        int idx = tid + i * 256;
        int m = idx >> 3, jl = idx & 7, jj = jb + jl;
        const float* G = g_gates + m * 3072;
        float gir = epi[m][jl], giz = epi[m][8 + jl], gin = epi[m][16 + jl];
        float ghr = G[1536 + jj], ghz = G[2048 + jj], ghn = G[2560 + jj];
        float r = sigmoidf_(gir + bih[jj]       + ghr + bhh[jj]);
        float z = sigmoidf_(giz + bih[512 + jj] + ghz + bhh[512 + jj]);
        float n = tanhf(gin + bih[1024 + jj] + r * (ghn + bhh[1024 + jj]));
        float hn = (1.f - z) * n + z * hOldf[m * DH + jj];
        int o = m * DH + jj;
        hNewf[o] = hn;
        __half hi = __float2half(hn);
        hNewh[o] = hi;
        hNewl[o] = __float2half(hn - __half2float(hi));
        if (isL1) {
            g_Ah[(m * NDRAFT + step) * DH + jj] = hi;
            if (step < NDRAFT - 1) {
                float xv = embed[(long)tids[m * NDRAFT + step] * DH + jj];
                __half xh = __float2half(xv);
                g_xh[o] = xh;
                g_xl[o] = __float2half(xv - __half2float(xh));
            }
        }
    }
}

// ---------------------------------------------------------------------------
__global__ __launch_bounds__(256) void gru_fused(
    const float* __restrict__ hidden, const int* __restrict__ tids,
    const float* __restrict__ ip_w,  const float* __restrict__ ip_b,
    const float* __restrict__ w_ih0, const float* __restrict__ w_hh0,
    const float* __restrict__ b_ih0, const float* __restrict__ b_hh0,
    const float* __restrict__ w_ih1, const float* __restrict__ w_hh1,
    const float* __restrict__ b_ih1, const float* __restrict__ b_hh1,
    const float* __restrict__ embed)
{
    __shared__ union { SmemIP ip; SmemGa g; float epi[64][25]; } sm;
    const int tid = threadIdx.x;
    const int c = blockIdx.x;

    // ---- phase -1: convert GRU weights to fp16 (once per call) ----
    for (int i = c * 256 + tid; i < G3 * DH; i += GRIDN * 256) {
        g_wih0h[i] = __float2half(w_ih0[i]);
        g_whh0h[i] = __float2half(w_hh0[i]);
        g_wih1h[i] = __float2half(w_ih1[i]);
        g_whh1h[i] = __float2half(w_hh1[i]);
    }

    // ---- phase 0: input projection partials (64x64 n-tile, 256-k slice) ----
    {
        const int n0 = (c & 7) * 64;
        const int kbase = (c >> 3) * 256;
        const int ty = tid >> 4, tx = tid & 15;
        float acc[4][4] = {};
        for (int kt = 0; kt < 256; kt += 32) {
            #pragma unroll
            for (int i = 0; i < 2; i++) {
                int f = tid + i * 256;
                int m = f >> 3;
                int kq = (f & 7) << 2;
                float4 va = *reinterpret_cast<const float4*>(&hidden[m * HID + kbase + kt + kq]);
                sm.ip.As[kq + 0][m] = va.x; sm.ip.As[kq + 1][m] = va.y;
                sm.ip.As[kq + 2][m] = va.z; sm.ip.As[kq + 3][m] = va.w;
                float4 vw = *reinterpret_cast<const float4*>(&ip_w[(n0 + m) * HID + kbase + kt + kq]);
                sm.ip.Ws[kq + 0][m] = vw.x; sm.ip.Ws[kq + 1][m] = vw.y;
                sm.ip.Ws[kq + 2][m] = vw.z; sm.ip.Ws[kq + 3][m] = vw.w;
            }
            __syncthreads();
            #pragma unroll
            for (int kk = 0; kk < 32; kk++) {
                float a[4], b[4];
                #pragma unroll
                for (int i = 0; i < 4; i++) { a[i] = sm.ip.As[kk][ty * 4 + i]; b[i] = sm.ip.Ws[kk][tx * 4 + i]; }
                #pragma unroll
                for (int i = 0; i < 4; i++)
                    #pragma unroll
                    for (int j = 0; j < 4; j++) acc[i][j] += a[i] * b[j];
            }
            __syncthreads();
        }
        float* part = g_part + (c >> 3) * (B_ * DH);
        #pragma unroll
        for (int i = 0; i < 4; i++)
            #pragma unroll
            for (int j = 0; j < 4; j++)
                part[(ty * 4 + i) * DH + n0 + tx * 4 + j] = acc[i][j];
    }
    grid_barrier(tid);

    // ---- phase 1: reduce 16 partials + bias; init slot 0 + x = 0 ----
    {
        int idx = c * 256 + tid;
        float s = 0.f;
        #pragma unroll
        for (int p = 0; p < 16; p++) s += g_part[p * (B_ * DH) + idx];
        s += ip_b[idx & (DH - 1)];
        g_h0f[0][idx] = s;
        g_h1f[0][idx] = s;
        __half hi = __float2half(s);
        __half lo = __float2half(s - __half2float(hi));
        g_h0h[0][idx] = hi; g_h0l[0][idx] = lo;
        g_h1h[0][idx] = hi; g_h1l[0][idx] = lo;
        g_xh[idx] = __float2half(0.f);
        g_xl[idx] = __float2half(0.f);
    }
    grid_barrier(tid);

    // ---- 4 draft steps x 2 GRU layers ----
    const bool isGH = (c >= 64);
    const int  pidx = c & 63;
    const int  jr   = pidx * 8;
    float (*epi)[25] = isGH ? nullptr : sm.epi;

    for (int step = 0; step < NDRAFT; step++) {
        const int p = step & 1;
        // layer 0: gi = x @ Wih0^T | gh = h0[p] @ Whh0^T -> h0[1-p]
        gates_mma(sm.g, tid, jr,
                  isGH ? g_h0h[p] : g_xh, isGH ? g_h0l[p] : g_xl,
                  isGH ? g_whh0h : g_wih0h, epi);
        pair_barrier(pidx, tid);
        if (!isGH)
            combine_gi(sm.epi, tid, jr, b_ih0, b_hh0,
                       g_h0f[p], g_h0f[1 - p], g_h0h[1 - p], g_h0l[1 - p],
                       false, step, tids, embed);
        grid_barrier(tid);
        // layer 1: gi = h0[1-p] @ Wih1^T | gh = h1[p] @ Whh1^T -> h1[1-p]
        gates_mma(sm.g, tid, jr,
                  isGH ? g_h1h[p] : g_h0h[1 - p], isGH ? g_h1l[p] : g_h0l[1 - p],
                  isGH ? g_whh1h : g_wih1h, epi);
        pair_barrier(pidx, tid);
        if (!isGH)
            combine_gi(sm.epi, tid, jr, b_ih1, b_hh1,
                       g_h1f[p], g_h1f[1 - p], g_h1h[1 - p], g_h1l[1 - p],
                       true, step, tids, embed);
        grid_barrier(tid);
    }
}

// ---------------------------------------------------------------------------
// Logits GEMM via single fp16 mma.sync (fp32 accum) — round-10..12 proven.
// CTA tile 128(M) x 128(N) x 32(K); 8 warps (2 M x 4 N); warp tile 64x32.
// smem 40KB -> 2 CTAs/SM. grid (2, 393).
// ---------------------------------------------------------------------------
#define ROWB 80
#define AH_OFF(s) ((s) * 10240)
#define BH_OFF(s) (20480 + (s) * 10240)
#define LOGITS_SMEM 40960

__global__ __launch_bounds__(256, 2) void logits_mma(const float* __restrict__ W,
                                                     float* __restrict__ out)
{
    extern __shared__ char smem[];
    const uint32_t sbase = smem_to_u32(smem);
    const int tid  = threadIdx.x;
    const int lane = tid & 31;
    const int w    = tid >> 5;
    const int wm   = w >> 2;
    const int wn   = w & 3;
    const int m0   = blockIdx.x * 128;
    const int n0   = blockIdx.y * 128;

    float d[4][4][4];
    #pragma unroll
    for (int i = 0; i < 4; i++)
        #pragma unroll
        for (int j = 0; j < 4; j++)
            #pragma unroll
            for (int q = 0; q < 4; q++) d[i][j][q] = 0.f;

    float4 breg[4];

    auto cpasync_A = [&](int c, int s) {
        const int k0 = c * 32;
        #pragma unroll
        for (int i = 0; i < 2; i++) {
            int idx = tid + i * 256;
            int row = idx >> 2;
            int ch  = idx & 3;
            const __half* sh = &g_Ah[(m0 + row) * DH + k0 + ch * 8];
            uint32_t dh = sbase + AH_OFF(s) + row * ROWB + ch * 16;
            asm volatile("cp.async.ca.shared.global [%0], [%1], 16;" :: "r"(dh), "l"(sh));
        }
        asm volatile("cp.async.commit_group;" ::: "memory");
    };

    auto ldg_B = [&](int c) {
        const int k0 = c * 32;
        #pragma unroll
        for (int i = 0; i < 4; i++) {
            int idx = tid + i * 256;
            int row = idx >> 3;
            int col = (idx & 7) * 4;
            int vr = n0 + row;
            breg[i] = (vr < VOCAB)
                ? *reinterpret_cast<const float4*>(&W[(long)vr * DH + k0 + col])
                : make_float4(0.f, 0.f, 0.f, 0.f);
        }
    };

    auto sts_B = [&](int s) {
        #pragma unroll
        for (int i = 0; i < 4; i++) {
            int idx = tid + i * 256;
            int row = idx >> 3;
            int col = (idx & 7) * 4;
            float4 v = breg[i];
            uint2 ph;
            ph.x = pack_f16x2(__float2half(v.x), __float2half(v.y));
            ph.y = pack_f16x2(__float2half(v.z), __float2half(v.w));
            *reinterpret_cast<uint2*>(smem + BH_OFF(s) + row * ROWB + col * 2) = ph;
        }
    };

    auto compute = [&](int s) {
        #pragma unroll
        for (int ks = 0; ks < 2; ks++) {
            uint32_t ah[4][4];
            #pragma unroll
            for (int mi = 0; mi < 4; mi++) {
                int row = wm * 64 + mi * 16 + (lane & 15);
                int kc  = ks * 32 + (lane >> 4) * 16;
                ldsm4(ah[mi], sbase + AH_OFF(s) + row * ROWB + kc);
            }
            uint32_t bh[4][2];
            #pragma unroll
            for (int nb = 0; nb < 2; nb++) {
                int gq  = lane >> 3;
                int row = wn * 32 + nb * 16 + (gq >> 1) * 8 + (lane & 7);
                int kc  = ks * 32 + (gq & 1) * 16;
                ldsm4(&bh[nb * 2][0], sbase + BH_OFF(s) + row * ROWB + kc);
            }
            #pragma unroll
            for (int mi = 0; mi < 4; mi++)
                #pragma unroll
                for (int ni = 0; ni < 4; ni++)
                    mma16816h(d[mi][ni], ah[mi], bh[ni]);
        }
    };

    cpasync_A(0, 0);
    ldg_B(0);
    sts_B(0);
    asm volatile("cp.async.wait_group 0;" ::: "memory");
    __syncthreads();

    #pragma unroll 1
    for (int c = 0; c < 16; c++) {
        int s = c & 1;
        if (c + 1 < 16) {
            cpasync_A(c + 1, 1 - s);
            ldg_B(c + 1);
        }
        compute(s);
        if (c + 1 < 16) {
            sts_B(1 - s);
            asm volatile("cp.async.wait_group 0;" ::: "memory");
        }
        __syncthreads();
    }

    const int g  = lane >> 2;
    const int i2 = (lane & 3) * 2;
    #pragma unroll
    for (int mi = 0; mi < 4; mi++) {
        int r0 = m0 + wm * 64 + mi * 16 + g;
        long rb0 = (long)r0 * VOCAB;
        long rb1 = (long)(r0 + 8) * VOCAB;
        #pragma unroll
        for (int ni = 0; ni < 4; ni++) {
            int col = n0 + wn * 32 + ni * 8 + i2;
            if (col < VOCAB) {
                out[rb0 + col] = d[mi][ni][0];
                out[rb1 + col] = d[mi][ni][2];
                if (col + 1 < VOCAB) {
                    out[rb0 + col + 1] = d[mi][ni][1];
                    out[rb1 + col + 1] = d[mi][ni][3];
                }
            }
        }
    }
}

// ---------------------------------------------------------------------------
extern "C" void kernel_launch(void* const* d_in, const int* in_sizes, int n_in,
                              void* d_out, int out_size)
{
    const float* hidden = (const float*)d_in[0];
    const int*   tids   = (const int*)  d_in[1];
    const float* ip_w   = (const float*)d_in[2];
    const float* ip_b   = (const float*)d_in[3];
    const float* w_ih0  = (const float*)d_in[4];
    const float* w_hh0  = (const float*)d_in[5];
    const float* b_ih0  = (const float*)d_in[6];
    const float* b_hh0  = (const float*)d_in[7];
    const float* w_ih1  = (const float*)d_in[8];
    const float* w_hh1  = (const float*)d_in[9];
    const float* b_ih1  = (const float*)d_in[10];
    const float* b_hh1  = (const float*)d_in[11];
    const float* embed  = (const float*)d_in[12];
    const float* out_w  = (const float*)d_in[13];
    float* out = (float*)d_out;

    cudaFuncSetAttribute(logits_mma, cudaFuncAttributeMaxDynamicSharedMemorySize, LOGITS_SMEM);

    gru_fused<<<GRIDN, 256>>>(hidden, tids, ip_w, ip_b,
                              w_ih0, w_hh0, b_ih0, b_hh0,
                              w_ih1, w_hh1, b_ih1, b_hh1, embed);

    logits_mma<<<dim3(2, (VOCAB + 127) / 128), 256, LOGITS_SMEM>>>(out_w, out);
}

// round 16
// speedup vs baseline: 1.1852x; 1.0437x over previous
#include <cuda_runtime.h>
#include <cuda_fp16.h>
#include <math.h>
#include <stdint.h>

// ---------------------------------------------------------------------------
// ReDrafterHead: 2-layer GRU draft head + big vocab projection.
// B=64, HIDDEN=4096, DH=512, VOCAB=50257, NUM_DRAFT=4.
//
// Round 16 (= round 12 + 3-stage cp.async ring in gates_mma):
//  - gates_mma: wait_group 1 with 3 smem stages -> L2 latency no longer
//    exposed per slab (round 12 waited on the load it just issued).
//  - phase -1 weight conversion vectorized (float4 -> fp16x2 stores).
//  - combine/barrier structure, ip, logits_mma identical to round 12.
// ---------------------------------------------------------------------------

#define B_      64
#define HID     4096
#define DH      512
#define VOCAB   50257
#define NDRAFT  4
#define GRIDN   128
#define G3      1536

__device__ float  g_h0[B_ * DH];
__device__ float  g_h1[B_ * DH];
__device__ __half g_h0h[B_ * DH], g_h0l[B_ * DH];
__device__ __half g_h1h[B_ * DH], g_h1l[B_ * DH];
__device__ __half g_xh[B_ * DH],  g_xl[B_ * DH];
__device__ float  g_gates[B_ * 3072];       // [m][gi r,z,n | gh r,z,n] x 512
__device__ float  g_part[16 * B_ * DH];     // ip split-K partials
__device__ __half g_Ah[B_ * NDRAFT * DH];   // logits A fp16, m = b*4+step
__device__ __half g_wih0h[G3 * DH], g_whh0h[G3 * DH];
__device__ __half g_wih1h[G3 * DH], g_whh1h[G3 * DH];
__device__ unsigned int g_bcount;           // monotonic barrier counter

__device__ __forceinline__ float sigmoidf_(float v) { return 1.0f / (1.0f + __expf(-v)); }

__device__ __forceinline__ uint32_t pack_f16x2(__half lo, __half hi) {
    return ((uint32_t)__half_as_ushort(hi) << 16) | (uint32_t)__half_as_ushort(lo);
}
__device__ __forceinline__ uint32_t smem_to_u32(const void* p) {
    uint32_t a;
    asm("{ .reg .u64 t; cvta.to.shared.u64 t, %1; cvt.u32.u64 %0, t; }" : "=r"(a) : "l"(p));
    return a;
}
__device__ __forceinline__ void ldsm4(uint32_t* r, uint32_t addr) {
    asm volatile("ldmatrix.sync.aligned.m8n8.x4.shared.b16 {%0,%1,%2,%3}, [%4];"
        : "=r"(r[0]), "=r"(r[1]), "=r"(r[2]), "=r"(r[3]) : "r"(addr));
}
__device__ __forceinline__ void mma16816h(float* d, const uint32_t* a, const uint32_t* b) {
    asm volatile("mma.sync.aligned.m16n8k16.row.col.f32.f16.f16.f32 "
        "{%0,%1,%2,%3}, {%4,%5,%6,%7}, {%8,%9}, {%0,%1,%2,%3};"
        : "+f"(d[0]), "+f"(d[1]), "+f"(d[2]), "+f"(d[3])
        : "r"(a[0]), "r"(a[1]), "r"(a[2]), "r"(a[3]), "r"(b[0]), "r"(b[1]));
}

// Grid-wide barrier: monotonic counter (graph-replay safe; GRIDN co-resident).
__device__ __forceinline__ void grid_barrier(int tid) {
    __syncthreads();
    if (tid == 0) {
        __threadfence();
        unsigned int old = atomicAdd(&g_bcount, 1u);
        unsigned int target = (old / GRIDN + 1u) * GRIDN;
        unsigned int v;
        do {
            asm volatile("ld.acquire.gpu.global.u32 %0, [%1];" : "=r"(v) : "l"(&g_bcount));
        } while (v < target);
    }
    __syncthreads();
}

// ---------------------------------------------------------------------------
struct SmemIP { float As[32][64]; float Ws[32][64]; };
// Gates HMMA: 3-stage ring, 80B rows (conflict-free ldsm).
// Stage stride 12800 B: AHI at +0, ALO at +5120, W at +10240.
struct SmemGa { char buf[3 * 12800]; };
#define GA_AHI(st) ((st) * 12800)
#define GA_ALO(st) ((st) * 12800 + 5120)
#define GA_W(st)   ((st) * 12800 + 10240)

// ---------------------------------------------------------------------------
// Gates GEMM via HMMA: C[64 x 24(pad 32)] = A[64 x 512] * W[24 x 512]^T.
// A = (Ahi + Alo) fp16 2-term; W fp16 single. 3-stage cp.async ring.
// 8 warps: wm = w>>2 (m32 half), wn = w&3 (n8 tile; wn==3 padding, no store)
// Output gate g (=wn) cols -> g_gates[m][ghOff + g*512 + jr + jj].
// ---------------------------------------------------------------------------
__device__ __forceinline__ void gates_mma(
    SmemGa& s, int tid, int jr, int ghOff,
    const __half* __restrict__ Ahi, const __half* __restrict__ Alo,
    const __half* __restrict__ Wg)
{
    const uint32_t sb = smem_to_u32(&s);
    const int lane = tid & 31;
    const int w  = tid >> 5;
    const int wm = w >> 2;     // 0..1
    const int wn = w & 3;      // 0..3
    const int ng = wn >> 1;    // n16 group
    const int p  = wn & 1;     // n8 within group
    const int gq = lane >> 3;

    float d[2][4] = {};

    const int arow = tid >> 2;             // 0..63
    const int ach  = tid & 3;              // 16B chunk
    int gidx = 0;
    if (tid < 128) {
        int r = tid >> 2;                  // 0..31
        int gate = (r < 24) ? (r >> 3) : 0;
        int jj   = (r < 24) ? (r & 7) : (r - 24);
        gidx = gate * 512 + jr + jj;
    }

    auto load_tile = [&](int t) {
        const int st = t % 3;
        const int k0 = t * 32;
        uint32_t da = sb + GA_AHI(st) + arow * 80 + ach * 16;
        asm volatile("cp.async.ca.shared.global [%0], [%1], 16;"
                     :: "r"(da), "l"(&Ahi[arow * DH + k0 + ach * 8]));
        uint32_t dl = sb + GA_ALO(st) + arow * 80 + ach * 16;
        asm volatile("cp.async.ca.shared.global [%0], [%1], 16;"
                     :: "r"(dl), "l"(&Alo[arow * DH + k0 + ach * 8]));
        if (tid < 128) {
            uint32_t dw = sb + GA_W(st) + (tid >> 2) * 80 + (tid & 3) * 16;
            asm volatile("cp.async.ca.shared.global [%0], [%1], 16;"
                         :: "r"(dw), "l"(&Wg[(long)gidx * DH + k0 + (tid & 3) * 8]));
        }
    };

    auto compute = [&](int t) {
        const int st = t % 3;
        #pragma unroll
        for (int ks = 0; ks < 2; ks++) {
            uint32_t ahi2[2][4], alo2[2][4], bt[4];
            #pragma unroll
            for (int mi = 0; mi < 2; mi++) {
                int row = wm * 32 + mi * 16 + (lane & 15);
                int kc  = ks * 32 + (lane >> 4) * 16;
                ldsm4(ahi2[mi], sb + GA_AHI(st) + row * 80 + kc);
                ldsm4(alo2[mi], sb + GA_ALO(st) + row * 80 + kc);
            }
            {
                int rowB = ng * 16 + (gq >> 1) * 8 + (lane & 7);
                int kcB  = ks * 32 + (gq & 1) * 16;
                ldsm4(bt, sb + GA_W(st) + rowB * 80 + kcB);
            }
            uint32_t bf[2] = { bt[2 * p], bt[2 * p + 1] };
            #pragma unroll
            for (int mi = 0; mi < 2; mi++) {
                mma16816h(d[mi], ahi2[mi], bf);
                mma16816h(d[mi], alo2[mi], bf);
            }
        }
    };

    // prologue: 2 stages in flight
    load_tile(0); asm volatile("cp.async.commit_group;" ::: "memory");
    load_tile(1); asm volatile("cp.async.commit_group;" ::: "memory");

    #pragma unroll 1
    for (int t = 0; t < 16; t++) {
        // stage t guaranteed complete (<=1 pending group = t+1's load)
        asm volatile("cp.async.wait_group 1;" ::: "memory");
        __syncthreads();
        compute(t);
        if (t + 2 < 16) load_tile(t + 2);
        asm volatile("cp.async.commit_group;" ::: "memory");
    }

    // epilogue: store gate columns (skip wn==3 padding)
    if (wn < 3) {
        const int colb = ghOff + wn * 512 + jr + (lane & 3) * 2;
        #pragma unroll
        for (int mi = 0; mi < 2; mi++) {
            int r = wm * 32 + mi * 16 + (lane >> 2);
            float* gr = g_gates + r * 3072;
            gr[colb]     = d[mi][0];
            gr[colb + 1] = d[mi][1];
            gr += 8 * 3072;
            gr[colb]     = d[mi][2];
            gr[colb + 1] = d[mi][3];
        }
    }
}

// combine: one (m, j) per thread (32768 threads exactly).
__device__ __forceinline__ void gru_combine_ph(
    int c, int tid, const float* __restrict__ bih, const float* __restrict__ bhh,
    float* __restrict__ h, __half* __restrict__ hh, __half* __restrict__ hl,
    bool isL1, int step,
    const int* __restrict__ tids, const float* __restrict__ embed)
{
    int idx = c * 256 + tid;
    int m = idx >> 9, j = idx & 511;
    const float* G = g_gates + m * 3072;
    float r = sigmoidf_(G[j]        + bih[j]        + G[1536 + j] + bhh[j]);
    float z = sigmoidf_(G[512 + j]  + bih[512 + j]  + G[2048 + j] + bhh[512 + j]);
    float n = tanhf(G[1024 + j] + bih[1024 + j] + r * (G[2560 + j] + bhh[1024 + j]));
    float hn = (1.f - z) * n + z * h[idx];
    h[idx] = hn;
    __half hi = __float2half(hn);
    hh[idx] = hi;
    hl[idx] = __float2half(hn - __half2float(hi));
    if (isL1) {
        g_Ah[(m * NDRAFT + step) * DH + j] = hi;
        if (step < NDRAFT - 1) {
            float xv = embed[(long)tids[m * NDRAFT + step] * DH + j];
            __half xh = __float2half(xv);
            g_xh[idx] = xh;
            g_xl[idx] = __float2half(xv - __half2float(xh));
        }
    }
}

// ---------------------------------------------------------------------------
__global__ __launch_bounds__(256) void gru_fused(
    const float* __restrict__ hidden, const int* __restrict__ tids,
    const float* __restrict__ ip_w,  const float* __restrict__ ip_b,
    const float* __restrict__ w_ih0, const float* __restrict__ w_hh0,
    const float* __restrict__ b_ih0, const float* __restrict__ b_hh0,
    const float* __restrict__ w_ih1, const float* __restrict__ w_hh1,
    const float* __restrict__ b_ih1, const float* __restrict__ b_hh1,
    const float* __restrict__ embed)
{
    __shared__ union { SmemIP ip; SmemGa g; } sm;
    const int tid = threadIdx.x;
    const int c = blockIdx.x;

    // ---- phase -1: convert GRU weights to fp16 (vectorized) ----
    for (int i4 = c * 256 + tid; i4 < (G3 * DH) / 4; i4 += GRIDN * 256) {
        int i = i4 * 4;
        float4 v;
        uint2 o;
        v = *reinterpret_cast<const float4*>(&w_ih0[i]);
        o.x = pack_f16x2(__float2half(v.x), __float2half(v.y));
        o.y = pack_f16x2(__float2half(v.z), __float2half(v.w));
        *reinterpret_cast<uint2*>(&g_wih0h[i]) = o;
        v = *reinterpret_cast<const float4*>(&w_hh0[i]);
        o.x = pack_f16x2(__float2half(v.x), __float2half(v.y));
        o.y = pack_f16x2(__float2half(v.z), __float2half(v.w));
        *reinterpret_cast<uint2*>(&g_whh0h[i]) = o;
        v = *reinterpret_cast<const float4*>(&w_ih1[i]);
        o.x = pack_f16x2(__float2half(v.x), __float2half(v.y));
        o.y = pack_f16x2(__float2half(v.z), __float2half(v.w));
        *reinterpret_cast<uint2*>(&g_wih1h[i]) = o;
        v = *reinterpret_cast<const float4*>(&w_hh1[i]);
        o.x = pack_f16x2(__float2half(v.x), __float2half(v.y));
        o.y = pack_f16x2(__float2half(v.z), __float2half(v.w));
        *reinterpret_cast<uint2*>(&g_whh1h[i]) = o;
    }

    // ---- phase 0: input projection partials (64x64 n-tile, 256-k slice) ----
    {
        const int n0 = (c & 7) * 64;
        const int kbase = (c >> 3) * 256;
        const int ty = tid >> 4, tx = tid & 15;
        float acc[4][4] = {};
        for (int kt = 0; kt < 256; kt += 32) {
            #pragma unroll
            for (int i = 0; i < 2; i++) {
                int f = tid + i * 256;
                int m = f >> 3;
                int kq = (f & 7) << 2;
                float4 va = *reinterpret_cast<const float4*>(&hidden[m * HID + kbase + kt + kq]);
                sm.ip.As[kq + 0][m] = va.x; sm.ip.As[kq + 1][m] = va.y;
                sm.ip.As[kq + 2][m] = va.z; sm.ip.As[kq + 3][m] = va.w;
                float4 vw = *reinterpret_cast<const float4*>(&ip_w[(n0 + m) * HID + kbase + kt + kq]);
                sm.ip.Ws[kq + 0][m] = vw.x; sm.ip.Ws[kq + 1][m] = vw.y;
                sm.ip.Ws[kq + 2][m] = vw.z; sm.ip.Ws[kq + 3][m] = vw.w;
            }
            __syncthreads();
            #pragma unroll
            for (int kk = 0; kk < 32; kk++) {
                float a[4], b[4];
                #pragma unroll
                for (int i = 0; i < 4; i++) { a[i] = sm.ip.As[kk][ty * 4 + i]; b[i] = sm.ip.Ws[kk][tx * 4 + i]; }
                #pragma unroll
                for (int i = 0; i < 4; i++)
                    #pragma unroll
                    for (int j = 0; j < 4; j++) acc[i][j] += a[i] * b[j];
            }
            __syncthreads();
        }
        float* part = g_part + (c >> 3) * (B_ * DH);
        #pragma unroll
        for (int i = 0; i < 4; i++)
            #pragma unroll
            for (int j = 0; j < 4; j++)
                part[(ty * 4 + i) * DH + n0 + tx * 4 + j] = acc[i][j];
    }
    grid_barrier(tid);

    // ---- phase 1: reduce 16 partials + bias; init fp16 copies + x = 0 ----
    {
        int idx = c * 256 + tid;
        float s = 0.f;
        #pragma unroll
        for (int p = 0; p < 16; p++) s += g_part[p * (B_ * DH) + idx];
        s += ip_b[idx & (DH - 1)];
        g_h0[idx] = s;
        g_h1[idx] = s;
        __half hi = __float2half(s);
        __half lo = __float2half(s - __half2float(hi));
        g_h0h[idx] = hi; g_h0l[idx] = lo;
        g_h1h[idx] = hi; g_h1l[idx] = lo;
        g_xh[idx] = __float2half(0.f);
        g_xl[idx] = __float2half(0.f);
    }
    grid_barrier(tid);

    // ---- 4 draft steps x 2 GRU layers; CTA is a gi- or gh-worker ----
    const bool isGH = (c >= 64);
    const int  jr   = (c & 63) * 8;
    const int  ghOff = isGH ? 1536 : 0;

    for (int step = 0; step < NDRAFT; step++) {
        // layer 0: gi = x @ w_ih0^T | gh = h0 @ w_hh0^T
        gates_mma(sm.g, tid, jr, ghOff,
                  isGH ? g_h0h : g_xh, isGH ? g_h0l : g_xl,
                  isGH ? g_whh0h : g_wih0h);
        grid_barrier(tid);
        gru_combine_ph(c, tid, b_ih0, b_hh0, g_h0, g_h0h, g_h0l, false, step, tids, embed);
        grid_barrier(tid);
        // layer 1: gi = h0_new @ w_ih1^T | gh = h1 @ w_hh1^T
        gates_mma(sm.g, tid, jr, ghOff,
                  isGH ? g_h1h : g_h0h, isGH ? g_h1l : g_h0l,
                  isGH ? g_whh1h : g_wih1h);
        grid_barrier(tid);
        gru_combine_ph(c, tid, b_ih1, b_hh1, g_h1, g_h1h, g_h1l, true, step, tids, embed);
        grid_barrier(tid);
    }
}

// ---------------------------------------------------------------------------
// Logits GEMM via single fp16 mma.sync (fp32 accum) — round-10..12 proven.
// CTA tile 128(M) x 128(N) x 32(K); 8 warps (2 M x 4 N); warp tile 64x32.
// smem 40KB -> 2 CTAs/SM. grid (2, 393).
// ---------------------------------------------------------------------------
#define ROWB 80
#define AH_OFF(s) ((s) * 10240)
#define BH_OFF(s) (20480 + (s) * 10240)
#define LOGITS_SMEM 40960

__global__ __launch_bounds__(256, 2) void logits_mma(const float* __restrict__ W,
                                                     float* __restrict__ out)
{
    extern __shared__ char smem[];
    const uint32_t sbase = smem_to_u32(smem);
    const int tid  = threadIdx.x;
    const int lane = tid & 31;
    const int w    = tid >> 5;
    const int wm   = w >> 2;
    const int wn   = w & 3;
    const int m0   = blockIdx.x * 128;
    const int n0   = blockIdx.y * 128;

    float d[4][4][4];
    #pragma unroll
    for (int i = 0; i < 4; i++)
        #pragma unroll
        for (int j = 0; j < 4; j++)
            #pragma unroll
            for (int q = 0; q < 4; q++) d[i][j][q] = 0.f;

    float4 breg[4];

    auto cpasync_A = [&](int c, int s) {
        const int k0 = c * 32;
        #pragma unroll
        for (int i = 0; i < 2; i++) {
            int idx = tid + i * 256;
            int row = idx >> 2;
            int ch  = idx & 3;
            const __half* sh = &g_Ah[(m0 + row) * DH + k0 + ch * 8];
            uint32_t dh = sbase + AH_OFF(s) + row * ROWB + ch * 16;
            asm volatile("cp.async.ca.shared.global [%0], [%1], 16;" :: "r"(dh), "l"(sh));
        }
        asm volatile("cp.async.commit_group;" ::: "memory");
    };

    auto ldg_B = [&](int c) {
        const int k0 = c * 32;
        #pragma unroll
        for (int i = 0; i < 4; i++) {
            int idx = tid + i * 256;
            int row = idx >> 3;
            int col = (idx & 7) * 4;
            int vr = n0 + row;
            breg[i] = (vr < VOCAB)
                ? *reinterpret_cast<const float4*>(&W[(long)vr * DH + k0 + col])
                : make_float4(0.f, 0.f, 0.f, 0.f);
        }
    };

    auto sts_B = [&](int s) {
        #pragma unroll
        for (int i = 0; i < 4; i++) {
            int idx = tid + i * 256;
            int row = idx >> 3;
            int col = (idx & 7) * 4;
            float4 v = breg[i];
            uint2 ph;
            ph.x = pack_f16x2(__float2half(v.x), __float2half(v.y));
            ph.y = pack_f16x2(__float2half(v.z), __float2half(v.w));
            *reinterpret_cast<uint2*>(smem + BH_OFF(s) + row * ROWB + col * 2) = ph;
        }
    };

    auto compute = [&](int s) {
        #pragma unroll
        for (int ks = 0; ks < 2; ks++) {
            uint32_t ah[4][4];
            #pragma unroll
            for (int mi = 0; mi < 4; mi++) {
                int row = wm * 64 + mi * 16 + (lane & 15);
                int kc  = ks * 32 + (lane >> 4) * 16;
                ldsm4(ah[mi], sbase + AH_OFF(s) + row * ROWB + kc);
            }
            uint32_t bh[4][2];
            #pragma unroll
            for (int nb = 0; nb < 2; nb++) {
                int gq  = lane >> 3;
                int row = wn * 32 + nb * 16 + (gq >> 1) * 8 + (lane & 7);
                int kc  = ks * 32 + (gq & 1) * 16;
                ldsm4(&bh[nb * 2][0], sbase + BH_OFF(s) + row * ROWB + kc);
            }
            #pragma unroll
            for (int mi = 0; mi < 4; mi++)
                #pragma unroll
                for (int ni = 0; ni < 4; ni++)
                    mma16816h(d[mi][ni], ah[mi], bh[ni]);
        }
    };

    cpasync_A(0, 0);
    ldg_B(0);
    sts_B(0);
    asm volatile("cp.async.wait_group 0;" ::: "memory");
    __syncthreads();

    #pragma unroll 1
    for (int c = 0; c < 16; c++) {
        int s = c & 1;
        if (c + 1 < 16) {
            cpasync_A(c + 1, 1 - s);
            ldg_B(c + 1);
        }
        compute(s);
        if (c + 1 < 16) {
            sts_B(1 - s);
            asm volatile("cp.async.wait_group 0;" ::: "memory");
        }
        __syncthreads();
    }

    const int g  = lane >> 2;
    const int i2 = (lane & 3) * 2;
    #pragma unroll
    for (int mi = 0; mi < 4; mi++) {
        int r0 = m0 + wm * 64 + mi * 16 + g;
        long rb0 = (long)r0 * VOCAB;
        long rb1 = (long)(r0 + 8) * VOCAB;
        #pragma unroll
        for (int ni = 0; ni < 4; ni++) {
            int col = n0 + wn * 32 + ni * 8 + i2;
            if (col < VOCAB) {
                out[rb0 + col] = d[mi][ni][0];
                out[rb1 + col] = d[mi][ni][2];
                if (col + 1 < VOCAB) {
                    out[rb0 + col + 1] = d[mi][ni][1];
                    out[rb1 + col + 1] = d[mi][ni][3];
                }
            }
        }
    }
}

// ---------------------------------------------------------------------------
extern "C" void kernel_launch(void* const* d_in, const int* in_sizes, int n_in,
                              void* d_out, int out_size)
{
    const float* hidden = (const float*)d_in[0];
    const int*   tids   = (const int*)  d_in[1];
    const float* ip_w   = (const float*)d_in[2];
    const float* ip_b   = (const float*)d_in[3];
    const float* w_ih0  = (const float*)d_in[4];
    const float* w_hh0  = (const float*)d_in[5];
    const float* b_ih0  = (const float*)d_in[6];
    const float* b_hh0  = (const float*)d_in[7];
    const float* w_ih1  = (const float*)d_in[8];
    const float* w_hh1  = (const float*)d_in[9];
    const float* b_ih1  = (const float*)d_in[10];
    const float* b_hh1  = (const float*)d_in[11];
    const float* embed  = (const float*)d_in[12];
    const float* out_w  = (const float*)d_in[13];
    float* out = (float*)d_out;

    cudaFuncSetAttribute(logits_mma, cudaFuncAttributeMaxDynamicSharedMemorySize, LOGITS_SMEM);

    gru_fused<<<GRIDN, 256>>>(hidden, tids, ip_w, ip_b,
                              w_ih0, w_hh0, b_ih0, b_hh0,
                              w_ih1, w_hh1, b_ih1, b_hh1, embed);

    logits_mma<<<dim3(2, (VOCAB + 127) / 128), 256, LOGITS_SMEM>>>(out_w, out);
}

// round 17
// speedup vs baseline: 1.2553x; 1.0592x over previous
#include <cuda_runtime.h>
#include <cuda_fp16.h>
#include <math.h>
#include <stdint.h>

// ---------------------------------------------------------------------------
// ReDrafterHead: 2-layer GRU draft head + big vocab projection.
// B=64, HIDDEN=4096, DH=512, VOCAB=50257, NUM_DRAFT=4.
//
// Round 17 (= round 16 + deeper pipelines):
//  - gates_mma: k-tile 64 (8 slabs, was 16), 3-stage ring, dynamic smem 69KB.
//  - logits_mma: A operand on a 3-stage ring (wait_group 1), smem 50KB.
//  - combine/barrier structure identical to round 16 (best).
// ---------------------------------------------------------------------------

#define B_      64
#define HID     4096
#define DH      512
#define VOCAB   50257
#define NDRAFT  4
#define GRIDN   128
#define G3      1536

__device__ float  g_h0[B_ * DH];
__device__ float  g_h1[B_ * DH];
__device__ __half g_h0h[B_ * DH], g_h0l[B_ * DH];
__device__ __half g_h1h[B_ * DH], g_h1l[B_ * DH];
__device__ __half g_xh[B_ * DH],  g_xl[B_ * DH];
__device__ float  g_gates[B_ * 3072];       // [m][gi r,z,n | gh r,z,n] x 512
__device__ float  g_part[16 * B_ * DH];     // ip split-K partials
__device__ __half g_Ah[B_ * NDRAFT * DH];   // logits A fp16, m = b*4+step
__device__ __half g_wih0h[G3 * DH], g_whh0h[G3 * DH];
__device__ __half g_wih1h[G3 * DH], g_whh1h[G3 * DH];
__device__ unsigned int g_bcount;           // monotonic barrier counter

__device__ __forceinline__ float sigmoidf_(float v) { return 1.0f / (1.0f + __expf(-v)); }

__device__ __forceinline__ uint32_t pack_f16x2(__half lo, __half hi) {
    return ((uint32_t)__half_as_ushort(hi) << 16) | (uint32_t)__half_as_ushort(lo);
}
__device__ __forceinline__ uint32_t smem_to_u32(const void* p) {
    uint32_t a;
    asm("{ .reg .u64 t; cvta.to.shared.u64 t, %1; cvt.u32.u64 %0, t; }" : "=r"(a) : "l"(p));
    return a;
}
__device__ __forceinline__ void ldsm4(uint32_t* r, uint32_t addr) {
    asm volatile("ldmatrix.sync.aligned.m8n8.x4.shared.b16 {%0,%1,%2,%3}, [%4];"
        : "=r"(r[0]), "=r"(r[1]), "=r"(r[2]), "=r"(r[3]) : "r"(addr));
}
__device__ __forceinline__ void mma16816h(float* d, const uint32_t* a, const uint32_t* b) {
    asm volatile("mma.sync.aligned.m16n8k16.row.col.f32.f16.f16.f32 "
        "{%0,%1,%2,%3}, {%4,%5,%6,%7}, {%8,%9}, {%0,%1,%2,%3};"
        : "+f"(d[0]), "+f"(d[1]), "+f"(d[2]), "+f"(d[3])
        : "r"(a[0]), "r"(a[1]), "r"(a[2]), "r"(a[3]), "r"(b[0]), "r"(b[1]));
}

// Grid-wide barrier: monotonic counter (graph-replay safe; GRIDN co-resident).
__device__ __forceinline__ void grid_barrier(int tid) {
    __syncthreads();
    if (tid == 0) {
        __threadfence();
        unsigned int old = atomicAdd(&g_bcount, 1u);
        unsigned int target = (old / GRIDN + 1u) * GRIDN;
        unsigned int v;
        do {
            asm volatile("ld.acquire.gpu.global.u32 %0, [%1];" : "=r"(v) : "l"(&g_bcount));
        } while (v < target);
    }
    __syncthreads();
}

// ---------------------------------------------------------------------------
// Dynamic smem for gru_fused: 3-stage ring, k-tile 64, 144B rows.
//   AHI: st*23040, ALO: +9216, W: +18432. total 69120.
// ip phase reuses [0, 16384).
#define GSTG 23040
#define GA_AHI(st) ((st) * GSTG)
#define GA_ALO(st) ((st) * GSTG + 9216)
#define GA_W(st)   ((st) * GSTG + 18432)
#define GRU_SMEM   69120

// ---------------------------------------------------------------------------
// Gates GEMM via HMMA: C[64 x 24(pad 32)] = A[64 x 512] * W[24 x 512]^T.
// A = (Ahi + Alo) fp16 2-term; W fp16 single. k-tile 64, 8 slabs, 3-stage.
// 8 warps: wm = w>>2 (m32 half), wn = w&3 (n8 tile; wn==3 padding, no store)
// ---------------------------------------------------------------------------
__device__ __forceinline__ void gates_mma(
    char* smem, int tid, int jr, int ghOff,
    const __half* __restrict__ Ahi, const __half* __restrict__ Alo,
    const __half* __restrict__ Wg)
{
    const uint32_t sb = smem_to_u32(smem);
    const int lane = tid & 31;
    const int w  = tid >> 5;
    const int wm = w >> 2;     // 0..1
    const int wn = w & 3;      // 0..3
    const int ng = wn >> 1;    // n16 group
    const int p  = wn & 1;     // n8 within group
    const int gq = lane >> 3;

    float d[2][4] = {};

    // loader indices: A rows 0..63, 8 chunks of 16B each (2 per thread);
    // W rows 0..31 (24 real), 8 chunks (1 per thread, all 256 threads).
    const int wr = tid >> 3;               // 0..31
    const int wc = tid & 7;
    const int gate = (wr < 24) ? (wr >> 3) : 0;
    const int jj   = (wr < 24) ? (wr & 7) : (wr - 24);
    const long gidx = (long)(gate * 512 + jr + jj) * DH;

    auto load_tile = [&](int t) {
        const int st = t % 3;
        const int k0 = t * 64;
        #pragma unroll
        for (int i = 0; i < 2; i++) {
            int f = tid + i * 256;
            int row = f >> 3;
            int ch  = f & 7;
            uint32_t da = sb + GA_AHI(st) + row * 144 + ch * 16;
            asm volatile("cp.async.ca.shared.global [%0], [%1], 16;"
                         :: "r"(da), "l"(&Ahi[row * DH + k0 + ch * 8]));
            uint32_t dl = sb + GA_ALO(st) + row * 144 + ch * 16;
            asm volatile("cp.async.ca.shared.global [%0], [%1], 16;"
                         :: "r"(dl), "l"(&Alo[row * DH + k0 + ch * 8]));
        }
        uint32_t dw = sb + GA_W(st) + wr * 144 + wc * 16;
        asm volatile("cp.async.ca.shared.global [%0], [%1], 16;"
                     :: "r"(dw), "l"(&Wg[gidx + k0 + wc * 8]));
    };

    auto compute = [&](int t) {
        const int st = t % 3;
        #pragma unroll
        for (int ks = 0; ks < 4; ks++) {
            uint32_t ahi2[2][4], alo2[2][4], bt[4];
            #pragma unroll
            for (int mi = 0; mi < 2; mi++) {
                int row = wm * 32 + mi * 16 + (lane & 15);
                int kc  = ks * 32 + (lane >> 4) * 16;
                ldsm4(ahi2[mi], sb + GA_AHI(st) + row * 144 + kc);
                ldsm4(alo2[mi], sb + GA_ALO(st) + row * 144 + kc);
            }
            {
                int rowB = ng * 16 + (gq >> 1) * 8 + (lane & 7);
                int kcB  = ks * 32 + (gq & 1) * 16;
                ldsm4(bt, sb + GA_W(st) + rowB * 144 + kcB);
            }
            uint32_t bf[2] = { bt[2 * p], bt[2 * p + 1] };
            #pragma unroll
            for (int mi = 0; mi < 2; mi++) {
                mma16816h(d[mi], ahi2[mi], bf);
                mma16816h(d[mi], alo2[mi], bf);
            }
        }
    };

    // prologue: 2 stages in flight
    load_tile(0); asm volatile("cp.async.commit_group;" ::: "memory");
    load_tile(1); asm volatile("cp.async.commit_group;" ::: "memory");

    #pragma unroll 1
    for (int t = 0; t < 8; t++) {
        asm volatile("cp.async.wait_group 1;" ::: "memory");
        __syncthreads();
        compute(t);
        if (t + 2 < 8) load_tile(t + 2);
        asm volatile("cp.async.commit_group;" ::: "memory");
    }

    // epilogue: store gate columns (skip wn==3 padding)
    if (wn < 3) {
        const int colb = ghOff + wn * 512 + jr + (lane & 3) * 2;
        #pragma unroll
        for (int mi = 0; mi < 2; mi++) {
            int r = wm * 32 + mi * 16 + (lane >> 2);
            float* gr = g_gates + r * 3072;
            gr[colb]     = d[mi][0];
            gr[colb + 1] = d[mi][1];
            gr += 8 * 3072;
            gr[colb]     = d[mi][2];
            gr[colb + 1] = d[mi][3];
        }
    }
}

// combine: one (m, j) per thread (32768 threads exactly).
__device__ __forceinline__ void gru_combine_ph(
    int c, int tid, const float* __restrict__ bih, const float* __restrict__ bhh,
    float* __restrict__ h, __half* __restrict__ hh, __half* __restrict__ hl,
    bool isL1, int step,
    const int* __restrict__ tids, const float* __restrict__ embed)
{
    int idx = c * 256 + tid;
    int m = idx >> 9, j = idx & 511;
    const float* G = g_gates + m * 3072;
    float r = sigmoidf_(G[j]        + bih[j]        + G[1536 + j] + bhh[j]);
    float z = sigmoidf_(G[512 + j]  + bih[512 + j]  + G[2048 + j] + bhh[512 + j]);
    float n = tanhf(G[1024 + j] + bih[1024 + j] + r * (G[2560 + j] + bhh[1024 + j]));
    float hn = (1.f - z) * n + z * h[idx];
    h[idx] = hn;
    __half hi = __float2half(hn);
    hh[idx] = hi;
    hl[idx] = __float2half(hn - __half2float(hi));
    if (isL1) {
        g_Ah[(m * NDRAFT + step) * DH + j] = hi;
        if (step < NDRAFT - 1) {
            float xv = embed[(long)tids[m * NDRAFT + step] * DH + j];
            __half xh = __float2half(xv);
            g_xh[idx] = xh;
            g_xl[idx] = __float2half(xv - __half2float(xh));
        }
    }
}

// ---------------------------------------------------------------------------
__global__ __launch_bounds__(256) void gru_fused(
    const float* __restrict__ hidden, const int* __restrict__ tids,
    const float* __restrict__ ip_w,  const float* __restrict__ ip_b,
    const float* __restrict__ w_ih0, const float* __restrict__ w_hh0,
    const float* __restrict__ b_ih0, const float* __restrict__ b_hh0,
    const float* __restrict__ w_ih1, const float* __restrict__ w_hh1,
    const float* __restrict__ b_ih1, const float* __restrict__ b_hh1,
    const float* __restrict__ embed)
{
    extern __shared__ char smem[];
    const int tid = threadIdx.x;
    const int c = blockIdx.x;

    // ---- phase -1: convert GRU weights to fp16 (vectorized) ----
    for (int i4 = c * 256 + tid; i4 < (G3 * DH) / 4; i4 += GRIDN * 256) {
        int i = i4 * 4;
        float4 v;
        uint2 o;
        v = *reinterpret_cast<const float4*>(&w_ih0[i]);
        o.x = pack_f16x2(__float2half(v.x), __float2half(v.y));
        o.y = pack_f16x2(__float2half(v.z), __float2half(v.w));
        *reinterpret_cast<uint2*>(&g_wih0h[i]) = o;
        v = *reinterpret_cast<const float4*>(&w_hh0[i]);
        o.x = pack_f16x2(__float2half(v.x), __float2half(v.y));
        o.y = pack_f16x2(__float2half(v.z), __float2half(v.w));
        *reinterpret_cast<uint2*>(&g_whh0h[i]) = o;
        v = *reinterpret_cast<const float4*>(&w_ih1[i]);
        o.x = pack_f16x2(__float2half(v.x), __float2half(v.y));
        o.y = pack_f16x2(__float2half(v.z), __float2half(v.w));
        *reinterpret_cast<uint2*>(&g_wih1h[i]) = o;
        v = *reinterpret_cast<const float4*>(&w_hh1[i]);
        o.x = pack_f16x2(__float2half(v.x), __float2half(v.y));
        o.y = pack_f16x2(__float2half(v.z), __float2half(v.w));
        *reinterpret_cast<uint2*>(&g_whh1h[i]) = o;
    }

    // ---- phase 0: input projection partials (64x64 n-tile, 256-k slice) ----
    {
        float (*As)[64] = reinterpret_cast<float(*)[64]>(smem);
        float (*Ws)[64] = reinterpret_cast<float(*)[64]>(smem + 8192);
        const int n0 = (c & 7) * 64;
        const int kbase = (c >> 3) * 256;
        const int ty = tid >> 4, tx = tid & 15;
        float acc[4][4] = {};
        for (int kt = 0; kt < 256; kt += 32) {
            #pragma unroll
            for (int i = 0; i < 2; i++) {
                int f = tid + i * 256;
                int m = f >> 3;
                int kq = (f & 7) << 2;
                float4 va = *reinterpret_cast<const float4*>(&hidden[m * HID + kbase + kt + kq]);
                As[kq + 0][m] = va.x; As[kq + 1][m] = va.y;
                As[kq + 2][m] = va.z; As[kq + 3][m] = va.w;
                float4 vw = *reinterpret_cast<const float4*>(&ip_w[(n0 + m) * HID + kbase + kt + kq]);
                Ws[kq + 0][m] = vw.x; Ws[kq + 1][m] = vw.y;
                Ws[kq + 2][m] = vw.z; Ws[kq + 3][m] = vw.w;
            }
            __syncthreads();
            #pragma unroll
            for (int kk = 0; kk < 32; kk++) {
                float a[4], b[4];
                #pragma unroll
                for (int i = 0; i < 4; i++) { a[i] = As[kk][ty * 4 + i]; b[i] = Ws[kk][tx * 4 + i]; }
                #pragma unroll
                for (int i = 0; i < 4; i++)
                    #pragma unroll
                    for (int j = 0; j < 4; j++) acc[i][j] += a[i] * b[j];
            }
            __syncthreads();
        }
        float* part = g_part + (c >> 3) * (B_ * DH);
        #pragma unroll
        for (int i = 0; i < 4; i++)
            #pragma unroll
            for (int j = 0; j < 4; j++)
                part[(ty * 4 + i) * DH + n0 + tx * 4 + j] = acc[i][j];
    }
    grid_barrier(tid);

    // ---- phase 1: reduce 16 partials + bias; init fp16 copies + x = 0 ----
    {
        int idx = c * 256 + tid;
        float s = 0.f;
        #pragma unroll
        for (int p = 0; p < 16; p++) s += g_part[p * (B_ * DH) + idx];
        s += ip_b[idx & (DH - 1)];
        g_h0[idx] = s;
        g_h1[idx] = s;
        __half hi = __float2half(s);
        __half lo = __float2half(s - __half2float(hi));
        g_h0h[idx] = hi; g_h0l[idx] = lo;
        g_h1h[idx] = hi; g_h1l[idx] = lo;
        g_xh[idx] = __float2half(0.f);
        g_xl[idx] = __float2half(0.f);
    }
    grid_barrier(tid);

    // ---- 4 draft steps x 2 GRU layers; CTA is a gi- or gh-worker ----
    const bool isGH = (c >= 64);
    const int  jr   = (c & 63) * 8;
    const int  ghOff = isGH ? 1536 : 0;

    for (int step = 0; step < NDRAFT; step++) {
        gates_mma(smem, tid, jr, ghOff,
                  isGH ? g_h0h : g_xh, isGH ? g_h0l : g_xl,
                  isGH ? g_whh0h : g_wih0h);
        grid_barrier(tid);
        gru_combine_ph(c, tid, b_ih0, b_hh0, g_h0, g_h0h, g_h0l, false, step, tids, embed);
        grid_barrier(tid);
        gates_mma(smem, tid, jr, ghOff,
                  isGH ? g_h1h : g_h0h, isGH ? g_h1l : g_h0l,
                  isGH ? g_whh1h : g_wih1h);
        grid_barrier(tid);
        gru_combine_ph(c, tid, b_ih1, b_hh1, g_h1, g_h1h, g_h1l, true, step, tids, embed);
        grid_barrier(tid);
    }
}

// ---------------------------------------------------------------------------
// Logits GEMM via single fp16 mma.sync (fp32 accum).
// CTA tile 128(M) x 128(N) x 32(K); 8 warps (2 M x 4 N); warp tile 64x32.
// A on a 3-stage cp.async ring (wait_group 1); B via LDG->cvt->STS double
// buffer. smem 50KB -> 2 CTAs/SM (reg-limited anyway). grid (2, 393).
// ---------------------------------------------------------------------------
#define ROWB 80
#define AH_OFF(s) ((s) * 10240)
#define BH_OFF(s) (30720 + (s) * 10240)
#define LOGITS_SMEM 51200

__global__ __launch_bounds__(256, 2) void logits_mma(const float* __restrict__ W,
                                                     float* __restrict__ out)
{
    extern __shared__ char smem[];
    const uint32_t sbase = smem_to_u32(smem);
    const int tid  = threadIdx.x;
    const int lane = tid & 31;
    const int w    = tid >> 5;
    const int wm   = w >> 2;
    const int wn   = w & 3;
    const int m0   = blockIdx.x * 128;
    const int n0   = blockIdx.y * 128;

    float d[4][4][4];
    #pragma unroll
    for (int i = 0; i < 4; i++)
        #pragma unroll
        for (int j = 0; j < 4; j++)
            #pragma unroll
            for (int q = 0; q < 4; q++) d[i][j][q] = 0.f;

    float4 breg[4];

    auto cpasync_A = [&](int c) {
        const int s = c % 3;
        const int k0 = c * 32;
        #pragma unroll
        for (int i = 0; i < 2; i++) {
            int idx = tid + i * 256;
            int row = idx >> 2;
            int ch  = idx & 3;
            const __half* sh = &g_Ah[(m0 + row) * DH + k0 + ch * 8];
            uint32_t dh = sbase + AH_OFF(s) + row * ROWB + ch * 16;
            asm volatile("cp.async.ca.shared.global [%0], [%1], 16;" :: "r"(dh), "l"(sh));
        }
    };

    auto ldg_B = [&](int c) {
        const int k0 = c * 32;
        #pragma unroll
        for (int i = 0; i < 4; i++) {
            int idx = tid + i * 256;
            int row = idx >> 3;
            int col = (idx & 7) * 4;
            int vr = n0 + row;
            breg[i] = (vr < VOCAB)
                ? *reinterpret_cast<const float4*>(&W[(long)vr * DH + k0 + col])
                : make_float4(0.f, 0.f, 0.f, 0.f);
        }
    };

    auto sts_B = [&](int s) {
        #pragma unroll
        for (int i = 0; i < 4; i++) {
            int idx = tid + i * 256;
            int row = idx >> 3;
            int col = (idx & 7) * 4;
            float4 v = breg[i];
            uint2 ph;
            ph.x = pack_f16x2(__float2half(v.x), __float2half(v.y));
            ph.y = pack_f16x2(__float2half(v.z), __float2half(v.w));
            *reinterpret_cast<uint2*>(smem + BH_OFF(s) + row * ROWB + col * 2) = ph;
        }
    };

    auto compute = [&](int c) {
        const int sA = c % 3;
        const int sB = c & 1;
        #pragma unroll
        for (int ks = 0; ks < 2; ks++) {
            uint32_t ah[4][4];
            #pragma unroll
            for (int mi = 0; mi < 4; mi++) {
                int row = wm * 64 + mi * 16 + (lane & 15);
                int kc  = ks * 32 + (lane >> 4) * 16;
                ldsm4(ah[mi], sbase + AH_OFF(sA) + row * ROWB + kc);
            }
            uint32_t bh[4][2];
            #pragma unroll
            for (int nb = 0; nb < 2; nb++) {
                int gq  = lane >> 3;
                int row = wn * 32 + nb * 16 + (gq >> 1) * 8 + (lane & 7);
                int kc  = ks * 32 + (gq & 1) * 16;
                ldsm4(&bh[nb * 2][0], sbase + BH_OFF(sB) + row * ROWB + kc);
            }
            #pragma unroll
            for (int mi = 0; mi < 4; mi++)
                #pragma unroll
                for (int ni = 0; ni < 4; ni++)
                    mma16816h(d[mi][ni], ah[mi], bh[ni]);
        }
    };

    // prologue: A stages 0,1 in flight; B stage 0 staged
    cpasync_A(0); asm volatile("cp.async.commit_group;" ::: "memory");
    cpasync_A(1); asm volatile("cp.async.commit_group;" ::: "memory");
    ldg_B(0);
    sts_B(0);
    asm volatile("cp.async.wait_group 1;" ::: "memory");
    __syncthreads();

    #pragma unroll 1
    for (int c = 0; c < 16; c++) {
        if (c + 2 < 16) cpasync_A(c + 2);
        asm volatile("cp.async.commit_group;" ::: "memory");
        if (c + 1 < 16) ldg_B(c + 1);
        compute(c);
        if (c + 1 < 16) {
            sts_B(1 - (c & 1));
            asm volatile("cp.async.wait_group 1;" ::: "memory");
        }
        __syncthreads();
    }

    const int g  = lane >> 2;
    const int i2 = (lane & 3) * 2;
    #pragma unroll
    for (int mi = 0; mi < 4; mi++) {
        int r0 = m0 + wm * 64 + mi * 16 + g;
        long rb0 = (long)r0 * VOCAB;
        long rb1 = (long)(r0 + 8) * VOCAB;
        #pragma unroll
        for (int ni = 0; ni < 4; ni++) {
            int col = n0 + wn * 32 + ni * 8 + i2;
            if (col < VOCAB) {
                out[rb0 + col] = d[mi][ni][0];
                out[rb1 + col] = d[mi][ni][2];
                if (col + 1 < VOCAB) {
                    out[rb0 + col + 1] = d[mi][ni][1];
                    out[rb1 + col + 1] = d[mi][ni][3];
                }
            }
        }
    }
}

// ---------------------------------------------------------------------------
extern "C" void kernel_launch(void* const* d_in, const int* in_sizes, int n_in,
                              void* d_out, int out_size)
{
    const float* hidden = (const float*)d_in[0];
    const int*   tids   = (const int*)  d_in[1];
    const float* ip_w   = (const float*)d_in[2];
    const float* ip_b   = (const float*)d_in[3];
    const float* w_ih0  = (const float*)d_in[4];
    const float* w_hh0  = (const float*)d_in[5];
    const float* b_ih0  = (const float*)d_in[6];
    const float* b_hh0  = (const float*)d_in[7];
    const float* w_ih1  = (const float*)d_in[8];
    const float* w_hh1  = (const float*)d_in[9];
    const float* b_ih1  = (const float*)d_in[10];
    const float* b_hh1  = (const float*)d_in[11];
    const float* embed  = (const float*)d_in[12];
    const float* out_w  = (const float*)d_in[13];
    float* out = (float*)d_out;

    cudaFuncSetAttribute(gru_fused, cudaFuncAttributeMaxDynamicSharedMemorySize, GRU_SMEM);
    cudaFuncSetAttribute(logits_mma, cudaFuncAttributeMaxDynamicSharedMemorySize, LOGITS_SMEM);

    gru_fused<<<GRIDN, 256, GRU_SMEM>>>(hidden, tids, ip_w, ip_b,
                                        w_ih0, w_hh0, b_ih0, b_hh0,
                                        w_ih1, w_hh1, b_ih1, b_hh1, embed);

    logits_mma<<<dim3(2, (VOCAB + 127) / 128), 256, LOGITS_SMEM>>>(out_w, out);
}